// round 12
// baseline (speedup 1.0000x reference)
#include <cuda_runtime.h>
#include <math.h>

#define BATCH     262144
#define MARGIN    1.0f
#define EPS_V     1e-6f
#define NBLOCKS   (BATCH / 4)   // 65536

// self-resetting cross-block accumulator state (static-init zero; each
// replay drains/resets it, so the graph needs no memset node)
__device__ float        g_accum = 0.0f;
__device__ unsigned int g_count = 0u;

__device__ __forceinline__ float dot4(float4 a, float4 b) {
    return fmaf(a.x, b.x, fmaf(a.y, b.y, fmaf(a.z, b.z, a.w * b.w)));
}

// One warp per triple; even warp = pos, odd warp = neg of the same element.
// 256 threads (8 warps, 4 elements) x 8 blocks/SM = 64 warps/SM resident.
__global__ __launch_bounds__(256, 8)
void transd_kernel(const float* __restrict__ ent,
                   const float* __restrict__ entp,
                   const float* __restrict__ rel,
                   const float* __restrict__ relp,
                   const int*   __restrict__ pos,
                   const int*   __restrict__ neg,
                   float*       __restrict__ out)
{
    const int lane = threadIdx.x & 31;
    const int warp = threadIdx.x >> 5;          // 0..7
    const int pair = warp >> 1;                 // 0..3
    const int elem = blockIdx.x * 4 + pair;     // batch element
    const bool is_neg = warp & 1;

    const int* __restrict__ tri = is_neg ? neg : pos;
    const int h = tri[elem * 3 + 0];
    const int r = tri[elem * 3 + 1];
    const int t = tri[elem * 3 + 2];

    const size_t lo = (size_t)lane;
    const float4* E  = (const float4*)ent;
    const float4* EP = (const float4*)entp;
    const float4* R  = (const float4*)rel;
    const float4* RP = (const float4*)relp;

    // all 6 gathers issued up front (MLP)
    float4 vh  = __ldg(E  + (size_t)h * 32 + lo);
    float4 vhp = __ldg(EP + (size_t)h * 32 + lo);
    float4 vt  = __ldg(E  + (size_t)t * 32 + lo);
    float4 vtp = __ldg(EP + (size_t)t * 32 + lo);
    float4 vr  = __ldg(R  + (size_t)r * 32 + lo);
    float4 vrp = __ldg(RP + (size_t)r * 32 + lo);

    // two dot partials, fused butterfly
    float sh = dot4(vhp, vh);
    float st = dot4(vtp, vt);
    #pragma unroll
    for (int o = 16; o > 0; o >>= 1) {
        sh += __shfl_xor_sync(0xFFFFFFFFu, sh, o);
        st += __shfl_xor_sync(0xFFFFFFFFu, st, o);
    }
    const float ds = sh - st;

    float dx = fmaf(vrp.x, ds, vh.x - vt.x + vr.x + EPS_V);
    float dy = fmaf(vrp.y, ds, vh.y - vt.y + vr.y + EPS_V);
    float dz = fmaf(vrp.z, ds, vh.z - vt.z + vr.z + EPS_V);
    float dw = fmaf(vrp.w, ds, vh.w - vt.w + vr.w + EPS_V);

    float ss = dx*dx + dy*dy + dz*dz + dw*dw;
    #pragma unroll
    for (int o = 16; o > 0; o >>= 1)
        ss += __shfl_xor_sync(0xFFFFFFFFu, ss, o);

    const float score = sqrtf(ss);

    __shared__ float scores[8];
    if (lane == 0) scores[warp] = score;
    __syncthreads();

    if (warp == 0) {
        float s = 0.0f;
        if (lane < 4) {
            float loss = scores[2 * lane] - scores[2 * lane + 1] + MARGIN;
            s = loss > 0.0f ? loss : 0.0f;
        }
        #pragma unroll
        for (int o = 2; o > 0; o >>= 1)
            s += __shfl_xor_sync(0xFFFFFFFFu, s, o);

        if (lane == 0) {
            atomicAdd(&g_accum, s);
            __threadfence();
            // wraps to 0 when old == NBLOCKS-1 -> counter auto-resets
            unsigned int old = atomicInc(&g_count, NBLOCKS - 1u);
            if (old == NBLOCKS - 1u) {
                // last block: drain + reset accumulator, publish result
                float total = atomicExch(&g_accum, 0.0f);
                out[0] = total * (1.0f / (float)BATCH);
            }
        }
    }
}

extern "C" void kernel_launch(void* const* d_in, const int* in_sizes, int n_in,
                              void* d_out, int out_size)
{
    const float* ent   = (const float*)d_in[0];
    const float* entp  = (const float*)d_in[1];
    const float* rel   = (const float*)d_in[2];
    const float* relp  = (const float*)d_in[3];
    const int*   pos_x = (const int*)d_in[4];
    const int*   neg_x = (const int*)d_in[5];
    float*       out   = (float*)d_out;

    transd_kernel<<<NBLOCKS, 256>>>(ent, entp, rel, relp, pos_x, neg_x, out);
}

// round 13
// speedup vs baseline: 1.1305x; 1.1305x over previous
#include <cuda_runtime.h>
#include <math.h>

#define BATCH     262144
#define MARGIN    1.0f
#define EPS_V     1e-6f

__device__ __forceinline__ float dot4(float4 a, float4 b) {
    return fmaf(a.x, b.x, fmaf(a.y, b.y, fmaf(a.z, b.z, a.w * b.w)));
}

// One warp per triple; even warp = pos, odd warp = neg of the same element.
// 256 threads (8 warps, 4 elements) x 8 blocks/SM = 64 warps/SM resident.
// Plain __ldg gathers; block-level atomicAdd (measured free at this grid);
// memset graph node zeroes the accumulator (measured free).
__global__ __launch_bounds__(256, 8)
void transd_kernel(const float* __restrict__ ent,
                   const float* __restrict__ entp,
                   const float* __restrict__ rel,
                   const float* __restrict__ relp,
                   const int*   __restrict__ pos,
                   const int*   __restrict__ neg,
                   float*       __restrict__ out)
{
    const int lane = threadIdx.x & 31;
    const int warp = threadIdx.x >> 5;          // 0..7
    const int pair = warp >> 1;                 // 0..3
    const int elem = blockIdx.x * 4 + pair;     // batch element
    const bool is_neg = warp & 1;

    const int* __restrict__ tri = is_neg ? neg : pos;
    const int h = tri[elem * 3 + 0];
    const int r = tri[elem * 3 + 1];
    const int t = tri[elem * 3 + 2];

    const size_t lo = (size_t)lane;
    const float4* E  = (const float4*)ent;
    const float4* EP = (const float4*)entp;
    const float4* R  = (const float4*)rel;
    const float4* RP = (const float4*)relp;

    // all 6 gathers issued up front (MLP)
    float4 vh  = __ldg(E  + (size_t)h * 32 + lo);
    float4 vhp = __ldg(EP + (size_t)h * 32 + lo);
    float4 vt  = __ldg(E  + (size_t)t * 32 + lo);
    float4 vtp = __ldg(EP + (size_t)t * 32 + lo);
    float4 vr  = __ldg(R  + (size_t)r * 32 + lo);
    float4 vrp = __ldg(RP + (size_t)r * 32 + lo);

    // two dot partials, fused butterfly
    float sh = dot4(vhp, vh);
    float st = dot4(vtp, vt);
    #pragma unroll
    for (int o = 16; o > 0; o >>= 1) {
        sh += __shfl_xor_sync(0xFFFFFFFFu, sh, o);
        st += __shfl_xor_sync(0xFFFFFFFFu, st, o);
    }
    const float ds = sh - st;

    float dx = fmaf(vrp.x, ds, vh.x - vt.x + vr.x + EPS_V);
    float dy = fmaf(vrp.y, ds, vh.y - vt.y + vr.y + EPS_V);
    float dz = fmaf(vrp.z, ds, vh.z - vt.z + vr.z + EPS_V);
    float dw = fmaf(vrp.w, ds, vh.w - vt.w + vr.w + EPS_V);

    float ss = dx*dx + dy*dy + dz*dz + dw*dw;
    #pragma unroll
    for (int o = 16; o > 0; o >>= 1)
        ss += __shfl_xor_sync(0xFFFFFFFFu, ss, o);

    const float score = sqrtf(ss);

    __shared__ float scores[8];
    if (lane == 0) scores[warp] = score;
    __syncthreads();

    if (warp == 0) {
        float s = 0.0f;
        if (lane < 4) {
            float loss = scores[2 * lane] - scores[2 * lane + 1] + MARGIN;
            s = loss > 0.0f ? loss : 0.0f;
        }
        #pragma unroll
        for (int o = 2; o > 0; o >>= 1)
            s += __shfl_xor_sync(0xFFFFFFFFu, s, o);
        if (lane == 0)
            atomicAdd(out, s * (1.0f / (float)BATCH));
    }
}

extern "C" void kernel_launch(void* const* d_in, const int* in_sizes, int n_in,
                              void* d_out, int out_size)
{
    const float* ent   = (const float*)d_in[0];
    const float* entp  = (const float*)d_in[1];
    const float* rel   = (const float*)d_in[2];
    const float* relp  = (const float*)d_in[3];
    const int*   pos_x = (const int*)d_in[4];
    const int*   neg_x = (const int*)d_in[5];
    float*       out   = (float*)d_out;

    cudaMemsetAsync(out, 0, sizeof(float));

    const int blocks = BATCH / 4;  // 4 elements per block, 8 warps
    transd_kernel<<<blocks, 256>>>(ent, entp, rel, relp, pos_x, neg_x, out);
}